// round 13
// baseline (speedup 1.0000x reference)
#include <cuda_runtime.h>
#include <cuda_fp16.h>
#include <cstdint>

#define LL      8192
#define BATCH   32
#define NF      128
#define NT      128
#define CPB     9             // CTAs per batch
#define NCTA    (CPB*BATCH)   // 288
#define NU      128           // k64 slabs per batch
#define NTH     256

// ---- global tables / scratch ----
__device__ __align__(16) float  g_lutc[LL];
__device__ __align__(16) float  g_luts[LL];
__device__ __align__(16) float  g_lutw[LL];
__device__ __align__(16) __half g_C[LL*NF];          // [u][f][64k] 16KB tiles
__device__ __align__(16) __half g_Wh[NT*LL];         // [t][l] fp16
__device__ __align__(16) __half g_sigh[BATCH*LL];    // fp16 signal
__device__ __align__(16) float  g_part[NCTA*NF*NT];  // 18.9MB, 1 segment/CTA
__device__ int g_cnt[BATCH];

// ---- smem: rows padded to 144B (64k halfs + 16B) => conflict-free ldsm ----
#define ROWB     144
#define TILEB    (128*ROWB)                // 18432
#define OFF_A(buf)  ((buf)*TILEB)
#define OFF_B(buf)  (2*TILEB + (buf)*TILEB)
#define SMEM_DYN    (4*TILEB)              // 73728 -> 2 CTAs/SM

// ---- PTX helpers ----
__device__ __forceinline__ uint32_t smem_u32(const void* p) {
    uint32_t a;
    asm("{ .reg .u64 t; cvta.to.shared.u64 t, %1; cvt.u32.u64 %0, t; }" : "=r"(a) : "l"(p));
    return a;
}
__device__ __forceinline__ void cpa16(uint32_t dst, const void* src) {
    asm volatile("cp.async.cg.shared.global [%0], [%1], 16;" :: "r"(dst), "l"(src));
}
#define CP_COMMIT() asm volatile("cp.async.commit_group;" ::: "memory")
#define CP_WAIT0()  asm volatile("cp.async.wait_group 0;" ::: "memory")

__device__ __forceinline__ void ldsm4(uint32_t r[4], uint32_t addr) {
    asm volatile("ldmatrix.sync.aligned.m8n8.x4.shared.b16 {%0,%1,%2,%3}, [%4];"
                 : "=r"(r[0]), "=r"(r[1]), "=r"(r[2]), "=r"(r[3]) : "r"(addr));
}
__device__ __forceinline__ void mma16816(float c[4], const uint32_t a[4],
                                         uint32_t b0, uint32_t b1) {
    asm volatile("mma.sync.aligned.m16n8k16.row.col.f32.f16.f16.f32 "
                 "{%0,%1,%2,%3}, {%4,%5,%6,%7}, {%8,%9}, {%0,%1,%2,%3};"
                 : "+f"(c[0]), "+f"(c[1]), "+f"(c[2]), "+f"(c[3])
                 : "r"(a[0]), "r"(a[1]), "r"(a[2]), "r"(a[3]), "r"(b0), "r"(b1));
}
__device__ __forceinline__ uint32_t hm2(uint32_t a, uint32_t b) {
    __half2 r = __hmul2(*(__half2*)&a, *(__half2*)&b);
    return *(uint32_t*)&r;
}
__device__ __forceinline__ float4 ldcg4(const float4* p) {
    float4 v;
    asm volatile("ld.global.cg.v4.f32 {%0,%1,%2,%3}, [%4];"
                 : "=f"(v.x), "=f"(v.y), "=f"(v.z), "=f"(v.w) : "l"(p));
    return v;
}

// ---------------------------------------------------------------------------
// LUTs (one transcendental per distinct argument) + counter reset each launch.
// ---------------------------------------------------------------------------
__global__ void prep_luts() {
    int i = blockIdx.x * blockDim.x + threadIdx.x;
    if (i < BATCH) g_cnt[i] = 0;
    if (i < LL) {
        float x = (float)i * (1.0f / 4096.0f);
        float s, c;
        sincospif(x, &s, &c);
        g_lutc[i] = c;
        g_luts[i] = s;
    } else if (i < 2 * LL) {
        int d = i - LL;
        float x = (float)d / 819.2f;
        g_lutw[d] = expf(-0.5f * (x * x));
    }
}

// ---------------------------------------------------------------------------
// Table fill via LUTs, 4 elements per thread.
// ---------------------------------------------------------------------------
__global__ void prep_tables(const float* __restrict__ sig) {
    int q = blockIdx.x * blockDim.x + threadIdx.x;
    const int nC = LL * NF / 4;
    const int nW = NT * LL / 4;
    if (q < nC) {
        int base = q * 4;
        int u = base >> 13;
        int r = base & 8191;
        int f = r >> 6;
        int c = r & 63;
        int fi = (f * 4096) / 127;
        float fv = (float)fi;
        const float TP = 6.2831854820251465f;
        const float DD = 1.7484556e-7f;
        float a  = TP * fv;
        float e1 = fmaf(TP, fv, -a);
        __half h[4];
#pragma unroll
        for (int i = 0; i < 4; i++) {
            int l = u * 64 + c + i;
            float lf = (float)l;
            float bb = a * lf;
            float e2 = fmaf(a, lf, -bb);
            float eps = (DD * (fv * lf) - e1 * lf - e2) * (1.0f / 8192.0f);
            int m = (fi * l) & (LL - 1);
            h[i] = __float2half_rn(g_lutc[m] - eps * g_luts[m]);
        }
        *(uint2*)&g_C[base] = *(uint2*)h;
    } else if (q < nC + nW) {
        int base = (q - nC) * 4;
        int t = base >> 13;
        int l = base & 8191;
        int tci = (t * 8191) / 127;
        __half h[4];
#pragma unroll
        for (int i = 0; i < 4; i++) {
            int d = l + i - tci; if (d < 0) d = -d;
            h[i] = __float2half_rn(g_lutw[d]);
        }
        *(uint2*)&g_Wh[base] = *(uint2*)h;
    } else if (q < nC + nW + BATCH * LL / 4) {
        int base = (q - nC - nW) * 4;
        float4 v = *(const float4*)&sig[base];
        __half h[4];
        h[0] = __float2half_rn(v.x); h[1] = __float2half_rn(v.y);
        h[2] = __float2half_rn(v.z); h[3] = __float2half_rn(v.w);
        *(uint2*)&g_sigh[base] = *(uint2*)h;
    }
}

// ---------------------------------------------------------------------------
// Batch-aligned GEMM + fused split-k reduce. CTA c: batch b=c/CPB, slab range
// [j*NU/CPB,(j+1)*NU/CPB). After storing its segment, the last CTA of each
// batch sums all 9 segments in fixed j order -> out (bit-identical to the old
// reduce_out kernel).
// ---------------------------------------------------------------------------
__global__ void __launch_bounds__(NTH, 2)
gabor_mma(float* __restrict__ out) {
    extern __shared__ __align__(16) char smc[];
    const uint32_t smb = smem_u32(smc);
    const int tid = threadIdx.x, lane = tid & 31, wid = tid >> 5;
    const int c = blockIdx.x;
    const int b = c / CPB, j = c - b * CPB;
    const int u0 = j * NU / CPB;
    const int u1 = (j + 1) * NU / CPB;

    auto copyA = [&](int u, int buf) {
        const char* src = (const char*)g_C + (size_t)u * 16384;
        const uint32_t dh = smb + OFF_A(buf);
#pragma unroll
        for (int r = 0; r < 4; r++) {
            int jj = tid + NTH * r;
            uint32_t doff = (uint32_t)(jj >> 3) * ROWB + (jj & 7) * 16;
            cpa16(dh + doff, src + jj * 16);
        }
    };

    const int tp = tid >> 1, qq = tid & 1;
    auto buildP = [&](int u, int buf) {
        const uint4* wp = (const uint4*)(g_Wh + (size_t)tp * LL + u * 64 + qq * 32);
        const uint4* sp = (const uint4*)(g_sigh + (size_t)b * LL + u * 64 + qq * 32);
        char* ph = smc + OFF_B(buf) + tp * ROWB + qq * 64;
#pragma unroll
        for (int m = 0; m < 4; m++) {
            uint4 w = wp[m], s = sp[m], p;
            p.x = hm2(w.x, s.x); p.y = hm2(w.y, s.y);
            p.z = hm2(w.z, s.z); p.w = hm2(w.w, s.w);
            *(uint4*)(ph + 16 * m) = p;
        }
    };

    copyA(u0, 0); CP_COMMIT();
    buildP(u0, 0);

    float acc[2][8][4];
#pragma unroll
    for (int m = 0; m < 2; m++)
#pragma unroll
        for (int n = 0; n < 8; n++)
#pragma unroll
            for (int q = 0; q < 4; q++) acc[m][n][q] = 0.0f;

    const int f0 = (wid & 3) * 32, t0 = (wid >> 2) * 64;
    const uint32_t loff = (uint32_t)(lane & 15) * ROWB + (lane >> 4) * 16;
    const int r0 = lane >> 2, c0 = (lane & 3) * 2;

    for (int u = u0; u < u1; u++) {
        CP_WAIT0();
        __syncthreads();
        const int buf = (u - u0) & 1;
        if (u + 1 < u1) {
            copyA(u + 1, buf ^ 1); CP_COMMIT();
            buildP(u + 1, buf ^ 1);
        }
        const uint32_t aH = smb + OFF_A(buf) + f0 * ROWB + loff;
        const uint32_t bH = smb + OFF_B(buf) + t0 * ROWB + loff;
#pragma unroll
        for (int k16 = 0; k16 < 4; k16++) {
            const uint32_t kb = k16 * 32;
            uint32_t ah[2][4], bh[4][4];
            ldsm4(ah[0], aH + kb); ldsm4(ah[1], aH + 16 * ROWB + kb);
#pragma unroll
            for (int jj = 0; jj < 4; jj++)
                ldsm4(bh[jj], bH + jj * 16 * ROWB + kb);
#pragma unroll
            for (int m = 0; m < 2; m++)
#pragma unroll
                for (int jj = 0; jj < 4; jj++) {
                    mma16816(acc[m][2 * jj],     ah[m], bh[jj][0], bh[jj][2]);
                    mma16816(acc[m][2 * jj + 1], ah[m], bh[jj][1], bh[jj][3]);
                }
        }
    }

    // ---- store own segment ----
    float* dst = g_part + (size_t)c * (NF * NT);
#pragma unroll
    for (int m = 0; m < 2; m++)
#pragma unroll
        for (int n = 0; n < 8; n++) {
            const int f = f0 + 16 * m + r0;
            const int t = t0 + 16 * (n >> 1) + 8 * (n & 1) + c0;
            *(float2*)&dst[f * NT + t]       = make_float2(acc[m][n][0], acc[m][n][1]);
            *(float2*)&dst[(f + 8) * NT + t] = make_float2(acc[m][n][2], acc[m][n][3]);
        }

    // ---- split-k semaphore: last CTA of batch b reduces ----
    __threadfence();
    __syncthreads();
    __shared__ int is_last;
    if (tid == 0) is_last = (atomicAdd(&g_cnt[b], 1) == CPB - 1) ? 1 : 0;
    __syncthreads();
    if (is_last) {
        const float4* base = (const float4*)(g_part + (size_t)b * CPB * (NF * NT));
        float4* ob = (float4*)(out + (size_t)b * (NF * NT));
        for (int i = tid; i < NF * NT / 4; i += NTH) {
            float4 a = ldcg4(base + i);
#pragma unroll
            for (int jj = 1; jj < CPB; jj++) {
                float4 v = ldcg4(base + (size_t)jj * (NF * NT / 4) + i);
                a.x += v.x; a.y += v.y; a.z += v.z; a.w += v.w;
            }
            ob[i] = a;
        }
    }
}

extern "C" void kernel_launch(void* const* d_in, const int* in_sizes, int n_in,
                              void* d_out, int out_size) {
    const float* sig = (const float*)d_in[0];
    float* out = (float*)d_out;

    prep_luts<<<(2 * LL + 255) / 256, 256>>>();

    int ptot = (2 * LL * 128 + BATCH * LL) / 4;
    prep_tables<<<(ptot + 255) / 256, 256>>>(sig);

    cudaFuncSetAttribute(gabor_mma, cudaFuncAttributeMaxDynamicSharedMemorySize, SMEM_DYN);
    gabor_mma<<<NCTA, NTH, SMEM_DYN>>>(out);
}

// round 14
// speedup vs baseline: 1.2187x; 1.2187x over previous
#include <cuda_runtime.h>
#include <cuda_fp16.h>
#include <cstdint>

#define LL      8192
#define BATCH   32
#define NF      128
#define NT      128
#define CPB     9             // CTAs per batch
#define NCTA    (CPB*BATCH)   // 288 <= 296 resident -> single wave, spin-safe
#define NU      128           // k64 slabs per batch
#define NTH     256

// ---- global tables / scratch ----
__device__ __align__(16) __half g_C[LL*NF];          // [u][f][64k] 16KB tiles
__device__ __align__(16) __half g_Wh[NT*LL];         // [t][l] fp16
__device__ __align__(16) __half g_sigh[BATCH*LL];    // fp16 signal
__device__ __align__(16) float  g_part[NCTA*NF*NT];  // 18.9MB (L2-resident)
__device__ int g_cnt[BATCH];

// ---- smem: rows padded to 144B (64k halfs + 16B) => conflict-free ldsm ----
#define ROWB     144
#define TILEB    (128*ROWB)                // 18432
#define OFF_A(buf)  ((buf)*TILEB)
#define OFF_B(buf)  (2*TILEB + (buf)*TILEB)
#define SMEM_DYN    (4*TILEB)              // 73728 -> 2 CTAs/SM

// ---- PTX helpers ----
__device__ __forceinline__ uint32_t smem_u32(const void* p) {
    uint32_t a;
    asm("{ .reg .u64 t; cvta.to.shared.u64 t, %1; cvt.u32.u64 %0, t; }" : "=r"(a) : "l"(p));
    return a;
}
__device__ __forceinline__ void cpa16(uint32_t dst, const void* src) {
    asm volatile("cp.async.cg.shared.global [%0], [%1], 16;" :: "r"(dst), "l"(src));
}
#define CP_COMMIT() asm volatile("cp.async.commit_group;" ::: "memory")
#define CP_WAIT0()  asm volatile("cp.async.wait_group 0;" ::: "memory")

__device__ __forceinline__ void ldsm4(uint32_t r[4], uint32_t addr) {
    asm volatile("ldmatrix.sync.aligned.m8n8.x4.shared.b16 {%0,%1,%2,%3}, [%4];"
                 : "=r"(r[0]), "=r"(r[1]), "=r"(r[2]), "=r"(r[3]) : "r"(addr));
}
__device__ __forceinline__ void mma16816(float c[4], const uint32_t a[4],
                                         uint32_t b0, uint32_t b1) {
    asm volatile("mma.sync.aligned.m16n8k16.row.col.f32.f16.f16.f32 "
                 "{%0,%1,%2,%3}, {%4,%5,%6,%7}, {%8,%9}, {%0,%1,%2,%3};"
                 : "+f"(c[0]), "+f"(c[1]), "+f"(c[2]), "+f"(c[3])
                 : "r"(a[0]), "r"(a[1]), "r"(a[2]), "r"(a[3]), "r"(b0), "r"(b1));
}
__device__ __forceinline__ uint32_t hm2(uint32_t a, uint32_t b) {
    __half2 r = __hmul2(*(__half2*)&a, *(__half2*)&b);
    return *(uint32_t*)&r;
}
__device__ __forceinline__ float4 ldcg4(const float4* p) {
    float4 v;
    asm volatile("ld.global.cg.v4.f32 {%0,%1,%2,%3}, [%4];"
                 : "=f"(v.x), "=f"(v.y), "=f"(v.z), "=f"(v.w) : "l"(p));
    return v;
}

// ---------------------------------------------------------------------------
// Single prep kernel (direct transcendentals), 4 elems/thread + counter zero.
// C fp16 [u][f][64k] tiles, exact fp32-phase replication; W fp16; sig fp16.
// ---------------------------------------------------------------------------
__global__ void prep_tables(const float* __restrict__ sig) {
    int q = blockIdx.x * blockDim.x + threadIdx.x;
    if (q < BATCH) g_cnt[q] = 0;
    const int nC = LL * NF / 4;
    const int nW = NT * LL / 4;
    if (q < nC) {
        int base = q * 4;
        int u = base >> 13;
        int r = base & 8191;
        int f = r >> 6;
        int c = r & 63;
        int fi = (f * 4096) / 127;
        float fv = (float)fi;
        const float TP = 6.2831854820251465f;
        const float DD = 1.7484556e-7f;
        float a  = TP * fv;
        float e1 = fmaf(TP, fv, -a);
        __half h[4];
#pragma unroll
        for (int i = 0; i < 4; i++) {
            int l = u * 64 + c + i;
            float lf = (float)l;
            float bb = a * lf;
            float e2 = fmaf(a, lf, -bb);
            float eps = (DD * (fv * lf) - e1 * lf - e2) * (1.0f / 8192.0f);
            int m = (fi * l) & (LL - 1);
            float x = (float)m * (1.0f / 4096.0f);
            float s, cc;
            sincospif(x, &s, &cc);
            h[i] = __float2half_rn(cc - eps * s);
        }
        *(uint2*)&g_C[base] = *(uint2*)h;
    } else if (q < nC + nW) {
        int base = (q - nC) * 4;
        int t = base >> 13;
        int l = base & 8191;
        int tci = (t * 8191) / 127;
        float tcf = (float)tci;
        __half h[4];
#pragma unroll
        for (int i = 0; i < 4; i++) {
            float x = ((float)(l + i) - tcf) / 819.2f;
            h[i] = __float2half_rn(expf(-0.5f * (x * x)));
        }
        *(uint2*)&g_Wh[base] = *(uint2*)h;
    } else if (q < nC + nW + BATCH * LL / 4) {
        int base = (q - nC - nW) * 4;
        float4 v = *(const float4*)&sig[base];
        __half h[4];
        h[0] = __float2half_rn(v.x); h[1] = __float2half_rn(v.y);
        h[2] = __float2half_rn(v.z); h[3] = __float2half_rn(v.w);
        *(uint2*)&g_sigh[base] = *(uint2*)h;
    }
}

// ---------------------------------------------------------------------------
// Batch-aligned GEMM + cooperative split-k reduce (single wave: 288<=296).
// CTA c: batch b=c/CPB, slabs [j*NU/CPB,(j+1)*NU/CPB). After its segment
// store, every CTA waits for its batch's 9 arrivals, then reduces 1/9 of the
// batch output in fixed j order (bit-identical to the old reduce kernel).
// ---------------------------------------------------------------------------
__global__ void __launch_bounds__(NTH, 2)
gabor_mma(float* __restrict__ out) {
    extern __shared__ __align__(16) char smc[];
    const uint32_t smb = smem_u32(smc);
    const int tid = threadIdx.x, lane = tid & 31, wid = tid >> 5;
    const int c = blockIdx.x;
    const int b = c / CPB, j = c - b * CPB;
    const int u0 = j * NU / CPB;
    const int u1 = (j + 1) * NU / CPB;

    auto copyA = [&](int u, int buf) {
        const char* src = (const char*)g_C + (size_t)u * 16384;
        const uint32_t dh = smb + OFF_A(buf);
#pragma unroll
        for (int r = 0; r < 4; r++) {
            int jj = tid + NTH * r;
            uint32_t doff = (uint32_t)(jj >> 3) * ROWB + (jj & 7) * 16;
            cpa16(dh + doff, src + jj * 16);
        }
    };

    const int tp = tid >> 1, qq = tid & 1;
    auto buildP = [&](int u, int buf) {
        const uint4* wp = (const uint4*)(g_Wh + (size_t)tp * LL + u * 64 + qq * 32);
        const uint4* sp = (const uint4*)(g_sigh + (size_t)b * LL + u * 64 + qq * 32);
        char* ph = smc + OFF_B(buf) + tp * ROWB + qq * 64;
#pragma unroll
        for (int m = 0; m < 4; m++) {
            uint4 w = wp[m], s = sp[m], p;
            p.x = hm2(w.x, s.x); p.y = hm2(w.y, s.y);
            p.z = hm2(w.z, s.z); p.w = hm2(w.w, s.w);
            *(uint4*)(ph + 16 * m) = p;
        }
    };

    copyA(u0, 0); CP_COMMIT();
    buildP(u0, 0);

    float acc[2][8][4];
#pragma unroll
    for (int m = 0; m < 2; m++)
#pragma unroll
        for (int n = 0; n < 8; n++)
#pragma unroll
            for (int q = 0; q < 4; q++) acc[m][n][q] = 0.0f;

    const int f0 = (wid & 3) * 32, t0 = (wid >> 2) * 64;
    const uint32_t loff = (uint32_t)(lane & 15) * ROWB + (lane >> 4) * 16;
    const int r0 = lane >> 2, c0 = (lane & 3) * 2;

    for (int u = u0; u < u1; u++) {
        CP_WAIT0();
        __syncthreads();
        const int buf = (u - u0) & 1;
        if (u + 1 < u1) {
            copyA(u + 1, buf ^ 1); CP_COMMIT();
            buildP(u + 1, buf ^ 1);
        }
        const uint32_t aH = smb + OFF_A(buf) + f0 * ROWB + loff;
        const uint32_t bH = smb + OFF_B(buf) + t0 * ROWB + loff;
#pragma unroll
        for (int k16 = 0; k16 < 4; k16++) {
            const uint32_t kb = k16 * 32;
            uint32_t ah[2][4], bh[4][4];
            ldsm4(ah[0], aH + kb); ldsm4(ah[1], aH + 16 * ROWB + kb);
#pragma unroll
            for (int jj = 0; jj < 4; jj++)
                ldsm4(bh[jj], bH + jj * 16 * ROWB + kb);
#pragma unroll
            for (int m = 0; m < 2; m++)
#pragma unroll
                for (int jj = 0; jj < 4; jj++) {
                    mma16816(acc[m][2 * jj],     ah[m], bh[jj][0], bh[jj][2]);
                    mma16816(acc[m][2 * jj + 1], ah[m], bh[jj][1], bh[jj][3]);
                }
        }
    }

    // ---- store own segment ----
    float* dst = g_part + (size_t)c * (NF * NT);
#pragma unroll
    for (int m = 0; m < 2; m++)
#pragma unroll
        for (int n = 0; n < 8; n++) {
            const int f = f0 + 16 * m + r0;
            const int t = t0 + 16 * (n >> 1) + 8 * (n & 1) + c0;
            *(float2*)&dst[f * NT + t]       = make_float2(acc[m][n][0], acc[m][n][1]);
            *(float2*)&dst[(f + 8) * NT + t] = make_float2(acc[m][n][2], acc[m][n][3]);
        }

    // ---- cooperative arrival + spin (single wave => deadlock-free) ----
    __syncthreads();                       // all CTA stores program-ordered
    if (tid == 0) {
        __threadfence();                   // release our segment
        atomicAdd(&g_cnt[b], 1);
        int v;
        do {
            asm volatile("ld.global.acquire.gpu.b32 %0, [%1];"
                         : "=r"(v) : "l"(&g_cnt[b]));
        } while (v < CPB);
    }
    __syncthreads();

    // ---- each of the 9 CTAs reduces its 1/9 slice of batch b (L2-hot) ----
    {
        const int n4b = NF * NT / 4;                 // 4096 float4 per batch
        const int s0 = j * n4b / CPB;
        const int s1 = (j + 1) * n4b / CPB;
        const float4* base = (const float4*)(g_part + (size_t)b * CPB * (NF * NT));
        float4* ob = (float4*)(out + (size_t)b * (NF * NT));
        for (int i = s0 + tid; i < s1; i += NTH) {
            float4 v0 = ldcg4(base + i);
            float4 v1 = ldcg4(base + 1 * n4b + i);
            float4 v2 = ldcg4(base + 2 * n4b + i);
            float4 v3 = ldcg4(base + 3 * n4b + i);
            float4 v4 = ldcg4(base + 4 * n4b + i);
            float4 v5 = ldcg4(base + 5 * n4b + i);
            float4 v6 = ldcg4(base + 6 * n4b + i);
            float4 v7 = ldcg4(base + 7 * n4b + i);
            float4 v8 = ldcg4(base + 8 * n4b + i);
            float4 a;
            a.x = ((((((((v0.x + v1.x) + v2.x) + v3.x) + v4.x) + v5.x) + v6.x) + v7.x) + v8.x);
            a.y = ((((((((v0.y + v1.y) + v2.y) + v3.y) + v4.y) + v5.y) + v6.y) + v7.y) + v8.y);
            a.z = ((((((((v0.z + v1.z) + v2.z) + v3.z) + v4.z) + v5.z) + v6.z) + v7.z) + v8.z);
            a.w = ((((((((v0.w + v1.w) + v2.w) + v3.w) + v4.w) + v5.w) + v6.w) + v7.w) + v8.w);
            ob[i] = a;
        }
    }
}

extern "C" void kernel_launch(void* const* d_in, const int* in_sizes, int n_in,
                              void* d_out, int out_size) {
    const float* sig = (const float*)d_in[0];
    float* out = (float*)d_out;

    int ptot = (2 * LL * 128 + BATCH * LL) / 4;
    prep_tables<<<(ptot + 255) / 256, 256>>>(sig);

    cudaFuncSetAttribute(gabor_mma, cudaFuncAttributeMaxDynamicSharedMemorySize, SMEM_DYN);
    gabor_mma<<<NCTA, NTH, SMEM_DYN>>>(out);
}